// round 1
// baseline (speedup 1.0000x reference)
#include <cuda_runtime.h>
#include <cstdint>

// Problem constants
#define N_BATCH 16
#define C_IN    256
#define H_IMG   128
#define W_IMG   128
#define GROUPS  8
#define CPG     32          // channels per group
#define KK      9           // 3x3 taps
#define OC      72          // GROUPS*KK
#define BN_EPS  1e-5f

// Logits / softmax-weights scratch: 16*72*128*128 floats = 75.5 MB
__device__ float g_logits[(size_t)N_BATCH * OC * H_IMG * W_IMG];

// ---------------- f32x2 helpers (Blackwell packed fp32 FMA) ----------------
__device__ __forceinline__ void fma2(unsigned long long& d,
                                     unsigned long long a,
                                     unsigned long long b) {
    asm("fma.rn.f32x2 %0, %1, %2, %0;" : "+l"(d) : "l"(a), "l"(b));
}
__device__ __forceinline__ unsigned long long pack2(float lo, float hi) {
    unsigned long long r;
    asm("mov.b64 %0, {%1, %2};" : "=l"(r) : "f"(lo), "f"(hi));
    return r;
}
__device__ __forceinline__ void unpack2(unsigned long long v, float& lo, float& hi) {
    asm("mov.b64 {%0, %1}, %2;" : "=f"(lo), "=f"(hi) : "l"(v));
}

__device__ __forceinline__ int refl(int v) {
    // ReflectionPad2d(1): -1 -> 1, 128 -> 126
    return v < 0 ? -v : (v > (H_IMG - 1) ? 2 * (H_IMG - 1) - v : v);
}

// ============================================================================
// K1: grouped conv 3x3 (reflect pad) + BN(inference) -> logits scratch
// Block: one (n, g), 16-row x 32-col pixel tile. 128 threads, 4 px/thread.
// ============================================================================
#define K1_TH 16
#define K1_TW 32
#define K1_XSTRIDE 35                     // 34 halo cols padded to 35
#define K1_WS_BYTES (KK * CPG * KK * 8)   // 2592 float2 = 20736 B
#define K1_XS_BYTES (16 * 18 * K1_XSTRIDE * 4)  // 40320 B
#define K1_SMEM (K1_WS_BYTES + K1_XS_BYTES)

__global__ void __launch_bounds__(128)
k1_conv_bn(const float* __restrict__ x,
           const float* __restrict__ w,
           const float* __restrict__ gamma,
           const float* __restrict__ beta,
           const float* __restrict__ mean,
           const float* __restrict__ var) {
    extern __shared__ char smem[];
    float2* ws2 = (float2*)smem;                       // [o][ci][tap], BN-scaled, duplicated
    float*  xs  = (float*)(smem + K1_WS_BYTES);        // [16][18][35]

    const int n  = blockIdx.z >> 3;
    const int g  = blockIdx.z & 7;
    const int bx = blockIdx.x * K1_TW;
    const int by = blockIdx.y * K1_TH;
    const int tid = threadIdx.x;
    const int row = tid >> 3;            // 0..15
    const int xq  = (tid & 7) << 2;      // 0,4,...,28

    // Stage BN-scaled duplicated weights: ws2[o*288 + ci*9 + t] = (w*scale, w*scale)
    for (int i = tid; i < KK * CPG * KK; i += 128) {
        int o  = i / (CPG * KK);
        int oc = g * KK + o;
        float sc = gamma[oc] * rsqrtf(var[oc] + BN_EPS);
        float wv = w[(size_t)oc * (CPG * KK) + (i % (CPG * KK))] * sc;
        ws2[i] = make_float2(wv, wv);
    }

    // Accumulators initialized with BN shift (beta - mean*scale)
    unsigned long long accA[9], accB[9];
#pragma unroll
    for (int o = 0; o < 9; o++) {
        int oc = g * KK + o;
        float sc = gamma[oc] * rsqrtf(var[oc] + BN_EPS);
        float sh = beta[oc] - mean[oc] * sc;
        accA[o] = pack2(sh, sh);
        accB[o] = pack2(sh, sh);
    }

    const float* xbase = x + (size_t)(n * C_IN + g * CPG) * (H_IMG * W_IMG);

#pragma unroll 1
    for (int chunk = 0; chunk < 2; chunk++) {
        __syncthreads();   // ws2 ready (iter 0) / previous xs consumed (iter 1)
        // Stage 16 channels, 18x34 reflected halo
        for (int i = tid; i < 16 * 18 * 34; i += 128) {
            int ci = i / (18 * 34);
            int rem = i % (18 * 34);
            int rr = rem / 34;
            int cc = rem % 34;
            int gy = refl(by + rr - 1);
            int gx = refl(bx + cc - 1);
            xs[ci * (18 * K1_XSTRIDE) + rr * K1_XSTRIDE + cc] =
                xbase[(size_t)(chunk * 16 + ci) * (H_IMG * W_IMG) + gy * W_IMG + gx];
        }
        __syncthreads();

#pragma unroll 1
        for (int ci = 0; ci < 16; ci++) {
            // 3 rows x 6 cols of x for this thread's 4-pixel strip
            float v[3][6];
            const float* xrow = xs + ci * (18 * K1_XSTRIDE) + row * K1_XSTRIDE + xq;
#pragma unroll
            for (int r3 = 0; r3 < 3; r3++)
#pragma unroll
                for (int c6 = 0; c6 < 6; c6++)
                    v[r3][c6] = xrow[r3 * K1_XSTRIDE + c6];

            unsigned long long pA[9], pB[9];
#pragma unroll
            for (int r3 = 0; r3 < 3; r3++)
#pragma unroll
                for (int c3 = 0; c3 < 3; c3++) {
                    pA[r3 * 3 + c3] = pack2(v[r3][c3],     v[r3][c3 + 1]);
                    pB[r3 * 3 + c3] = pack2(v[r3][c3 + 2], v[r3][c3 + 3]);
                }

            const int cig = chunk * 16 + ci;
            const unsigned long long* wbase =
                (const unsigned long long*)(ws2 + cig * KK);
#pragma unroll
            for (int o = 0; o < 9; o++) {
#pragma unroll
                for (int t = 0; t < 9; t++) {
                    unsigned long long wv = wbase[o * (CPG * KK) + t];  // broadcast LDS.64
                    fma2(accA[o], pA[t], wv);
                    fma2(accB[o], pB[t], wv);
                }
            }
        }
    }

    // Store logits: float4 per output channel
    float* lp = g_logits + ((size_t)(n * OC + g * KK) * H_IMG + (by + row)) * W_IMG + bx + xq;
#pragma unroll
    for (int o = 0; o < 9; o++) {
        float4 r;
        unpack2(accA[o], r.x, r.y);
        unpack2(accB[o], r.z, r.w);
        *(float4*)(lp + (size_t)o * (H_IMG * W_IMG)) = r;
    }
}

// ============================================================================
// K3: softmax over 72 channels (in-thread, per-pixel) + weighted 3x3 gather
// Block: one n, 16x16 pixel tile, 256 threads (1 px/thread).
// ============================================================================
#define K3_XSTRIDE 19
#define K3_LG_BYTES (OC * 256 * 4)                  // 73728 B
#define K3_XS_BYTES (16 * 18 * K3_XSTRIDE * 4)      // 21888 B
#define K3_SMEM (K3_LG_BYTES + K3_XS_BYTES)

__global__ void __launch_bounds__(256)
k3_softmax_gather(const float* __restrict__ x, float* __restrict__ out) {
    extern __shared__ char smem[];
    float* lg = (float*)smem;                        // [72][256]
    float* xs = (float*)(smem + K3_LG_BYTES);        // [16][18][19]

    const int n  = blockIdx.z;
    const int bx = blockIdx.x * 16;
    const int by = blockIdx.y * 16;
    const int tid = threadIdx.x;
    const int ty = tid >> 4;
    const int tx = tid & 15;

    // Load this pixel's 72 logits into this thread's shared column
    const float* lbase = g_logits + ((size_t)n * OC * H_IMG + (by + ty)) * W_IMG + bx + tx;
#pragma unroll
    for (int ch = 0; ch < OC; ch++)
        lg[ch * 256 + tid] = lbase[(size_t)ch * (H_IMG * W_IMG)];

    // Softmax over own column (no cross-thread data -> no sync needed for lg)
    float m = -1e30f;
#pragma unroll
    for (int ch = 0; ch < OC; ch++) m = fmaxf(m, lg[ch * 256 + tid]);
    float s = 0.f;
#pragma unroll
    for (int ch = 0; ch < OC; ch++) {
        float e = __expf(lg[ch * 256 + tid] - m);
        lg[ch * 256 + tid] = e;
        s += e;
    }
    const float inv = 1.0f / s;

    const float* xb = x + (size_t)n * C_IN * (H_IMG * W_IMG);
    float* ob = out + (size_t)n * C_IN * (H_IMG * W_IMG);

#pragma unroll 1
    for (int g = 0; g < 8; g++) {
        float sig[9];
#pragma unroll
        for (int k = 0; k < 9; k++) sig[k] = lg[(g * 9 + k) * 256 + tid] * inv;

#pragma unroll 1
        for (int chunk = 0; chunk < 2; chunk++) {
            __syncthreads();   // previous xs consumed
            for (int i = tid; i < 16 * 18 * 18; i += 256) {
                int ci = i / (18 * 18);
                int rem = i % (18 * 18);
                int rr = rem / 18;
                int cc = rem % 18;
                int gy = refl(by + rr - 1);
                int gx = refl(bx + cc - 1);
                xs[ci * (18 * K3_XSTRIDE) + rr * K3_XSTRIDE + cc] =
                    xb[(size_t)(g * CPG + chunk * 16 + ci) * (H_IMG * W_IMG) + gy * W_IMG + gx];
            }
            __syncthreads();

#pragma unroll 1
            for (int ci = 0; ci < 16; ci++) {
                const float* xp = xs + ci * (18 * K3_XSTRIDE) + ty * K3_XSTRIDE + tx;
                float acc = 0.f;
#pragma unroll
                for (int r3 = 0; r3 < 3; r3++)
#pragma unroll
                    for (int c3 = 0; c3 < 3; c3++)
                        acc += sig[r3 * 3 + c3] * xp[r3 * K3_XSTRIDE + c3];
                ob[(size_t)(g * CPG + chunk * 16 + ci) * (H_IMG * W_IMG)
                   + (by + ty) * W_IMG + bx + tx] = acc;
            }
        }
    }
}

// ============================================================================
extern "C" void kernel_launch(void* const* d_in, const int* in_sizes, int n_in,
                              void* d_out, int out_size) {
    const float* x     = (const float*)d_in[0];
    const float* w     = (const float*)d_in[1];
    const float* gamma = (const float*)d_in[2];
    const float* beta  = (const float*)d_in[3];
    const float* mean  = (const float*)d_in[4];
    const float* var   = (const float*)d_in[5];
    float* out = (float*)d_out;

    cudaFuncSetAttribute(k1_conv_bn,
                         cudaFuncAttributeMaxDynamicSharedMemorySize, K1_SMEM);
    cudaFuncSetAttribute(k3_softmax_gather,
                         cudaFuncAttributeMaxDynamicSharedMemorySize, K3_SMEM);

    dim3 g1(W_IMG / K1_TW, H_IMG / K1_TH, N_BATCH * GROUPS);   // (4, 8, 128)
    k1_conv_bn<<<g1, 128, K1_SMEM>>>(x, w, gamma, beta, mean, var);

    dim3 g3(W_IMG / 16, H_IMG / 16, N_BATCH);                  // (8, 8, 16)
    k3_softmax_gather<<<g3, 256, K3_SMEM>>>(x, out);
}

// round 2
// speedup vs baseline: 1.4385x; 1.4385x over previous
#include <cuda_runtime.h>
#include <cstdint>

// Problem constants
#define N_BATCH 16
#define C_IN    256
#define H_IMG   128
#define W_IMG   128
#define GROUPS  8
#define CPG     32          // channels per group
#define KK      9           // 3x3 taps
#define OC      72          // GROUPS*KK
#define BN_EPS  1e-5f

// Logits / softmax-weights scratch: 16*72*128*128 floats = 75.5 MB
__device__ float g_logits[(size_t)N_BATCH * OC * H_IMG * W_IMG];

// ---------------- f32x2 helpers (Blackwell packed fp32 FMA) ----------------
__device__ __forceinline__ void fma2(unsigned long long& d,
                                     unsigned long long a,
                                     unsigned long long b) {
    asm("fma.rn.f32x2 %0, %1, %2, %0;" : "+l"(d) : "l"(a), "l"(b));
}
__device__ __forceinline__ unsigned long long pack2(float lo, float hi) {
    unsigned long long r;
    asm("mov.b64 %0, {%1, %2};" : "=l"(r) : "f"(lo), "f"(hi));
    return r;
}
__device__ __forceinline__ void unpack2(unsigned long long v, float& lo, float& hi) {
    asm("mov.b64 {%0, %1}, %2;" : "=f"(lo), "=f"(hi) : "l"(v));
}

__device__ __forceinline__ int refl(int v) {
    // ReflectionPad2d(1): -1 -> 1, 128 -> 126
    return v < 0 ? -v : (v > (H_IMG - 1) ? 2 * (H_IMG - 1) - v : v);
}

// ============================================================================
// K1: grouped conv 3x3 (reflect pad) + BN(inference) -> logits scratch
// Block: one (n, g), 16-row x 32-col pixel tile. 128 threads, 4 px/thread.
// (unchanged from R1)
// ============================================================================
#define K1_TH 16
#define K1_TW 32
#define K1_XSTRIDE 35                     // 34 halo cols padded to 35
#define K1_WS_BYTES (KK * CPG * KK * 8)   // 2592 float2 = 20736 B
#define K1_XS_BYTES (16 * 18 * K1_XSTRIDE * 4)  // 40320 B
#define K1_SMEM (K1_WS_BYTES + K1_XS_BYTES)

__global__ void __launch_bounds__(128)
k1_conv_bn(const float* __restrict__ x,
           const float* __restrict__ w,
           const float* __restrict__ gamma,
           const float* __restrict__ beta,
           const float* __restrict__ mean,
           const float* __restrict__ var) {
    extern __shared__ char smem[];
    float2* ws2 = (float2*)smem;                       // [o][ci][tap], BN-scaled, duplicated
    float*  xs  = (float*)(smem + K1_WS_BYTES);        // [16][18][35]

    const int n  = blockIdx.z >> 3;
    const int g  = blockIdx.z & 7;
    const int bx = blockIdx.x * K1_TW;
    const int by = blockIdx.y * K1_TH;
    const int tid = threadIdx.x;
    const int row = tid >> 3;            // 0..15
    const int xq  = (tid & 7) << 2;      // 0,4,...,28

    // Stage BN-scaled duplicated weights
    for (int i = tid; i < KK * CPG * KK; i += 128) {
        int o  = i / (CPG * KK);
        int oc = g * KK + o;
        float sc = gamma[oc] * rsqrtf(var[oc] + BN_EPS);
        float wv = w[(size_t)oc * (CPG * KK) + (i % (CPG * KK))] * sc;
        ws2[i] = make_float2(wv, wv);
    }

    // Accumulators initialized with BN shift (beta - mean*scale)
    unsigned long long accA[9], accB[9];
#pragma unroll
    for (int o = 0; o < 9; o++) {
        int oc = g * KK + o;
        float sc = gamma[oc] * rsqrtf(var[oc] + BN_EPS);
        float sh = beta[oc] - mean[oc] * sc;
        accA[o] = pack2(sh, sh);
        accB[o] = pack2(sh, sh);
    }

    const float* xbase = x + (size_t)(n * C_IN + g * CPG) * (H_IMG * W_IMG);

#pragma unroll 1
    for (int chunk = 0; chunk < 2; chunk++) {
        __syncthreads();
        for (int i = tid; i < 16 * 18 * 34; i += 128) {
            int ci = i / (18 * 34);
            int rem = i % (18 * 34);
            int rr = rem / 34;
            int cc = rem % 34;
            int gy = refl(by + rr - 1);
            int gx = refl(bx + cc - 1);
            xs[ci * (18 * K1_XSTRIDE) + rr * K1_XSTRIDE + cc] =
                xbase[(size_t)(chunk * 16 + ci) * (H_IMG * W_IMG) + gy * W_IMG + gx];
        }
        __syncthreads();

#pragma unroll 1
        for (int ci = 0; ci < 16; ci++) {
            float v[3][6];
            const float* xrow = xs + ci * (18 * K1_XSTRIDE) + row * K1_XSTRIDE + xq;
#pragma unroll
            for (int r3 = 0; r3 < 3; r3++)
#pragma unroll
                for (int c6 = 0; c6 < 6; c6++)
                    v[r3][c6] = xrow[r3 * K1_XSTRIDE + c6];

            unsigned long long pA[9], pB[9];
#pragma unroll
            for (int r3 = 0; r3 < 3; r3++)
#pragma unroll
                for (int c3 = 0; c3 < 3; c3++) {
                    pA[r3 * 3 + c3] = pack2(v[r3][c3],     v[r3][c3 + 1]);
                    pB[r3 * 3 + c3] = pack2(v[r3][c3 + 2], v[r3][c3 + 3]);
                }

            const int cig = chunk * 16 + ci;
            const unsigned long long* wbase =
                (const unsigned long long*)(ws2 + cig * KK);
#pragma unroll
            for (int o = 0; o < 9; o++) {
#pragma unroll
                for (int t = 0; t < 9; t++) {
                    unsigned long long wv = wbase[o * (CPG * KK) + t];
                    fma2(accA[o], pA[t], wv);
                    fma2(accB[o], pB[t], wv);
                }
            }
        }
    }

    float* lp = g_logits + ((size_t)(n * OC + g * KK) * H_IMG + (by + row)) * W_IMG + bx + xq;
#pragma unroll
    for (int o = 0; o < 9; o++) {
        float4 r;
        unpack2(accA[o], r.x, r.y);
        unpack2(accB[o], r.z, r.w);
        *(float4*)(lp + (size_t)o * (H_IMG * W_IMG)) = r;
    }
}

// ============================================================================
// K3 (rewritten): softmax over 72 channels + weighted 3x3 gather
// Block: one n, 8-row x 32-col pixel tile, 256 threads, 1 px/thread.
// Warp = one full pixel row -> conflict-free LDS with immediate offsets.
// Precomputed reflect-address tables kill all per-element div/mod.
// ============================================================================
#define K3_TW 32
#define K3_TH 8
#define K3_HALO_R 10
#define K3_HALO_C 34
#define K3_NQ (K3_HALO_R * K3_HALO_C)    // 340 halo elements per channel
#define K3_CSTRIDE 352                   // 10*35 padded channel stride (words)
#define K3_RSTRIDE 35                    // row stride inside channel (words)

#define K3_LG_BYTES  (OC * 256 * 4)              // 73728 B
#define K3_XS_BYTES  (16 * K3_CSTRIDE * 4)       // 22528 B
#define K3_TAB_BYTES (K3_NQ * 4)                 // 1360 B each
#define K3_SMEM (K3_LG_BYTES + K3_XS_BYTES + 2 * K3_TAB_BYTES)

__global__ void __launch_bounds__(256, 2)
k3_softmax_gather(const float* __restrict__ x, float* __restrict__ out) {
    extern __shared__ char smem[];
    float* lg  = (float*)smem;                                    // [72][256] exp values
    float* xs  = (float*)(smem + K3_LG_BYTES);                    // [16][K3_CSTRIDE]
    int*   src = (int*)(smem + K3_LG_BYTES + K3_XS_BYTES);        // [340] global offsets
    int*   dst = src + K3_NQ;                                     // [340] smem offsets

    const int n  = blockIdx.z;
    const int bx = blockIdx.x * K3_TW;
    const int by = blockIdx.y * K3_TH;
    const int tid = threadIdx.x;
    const int ty = tid >> 5;             // 0..7
    const int tx = tid & 31;             // 0..31

    // Build reflect-address tables (one-time; divides amortized)
    for (int q = tid; q < K3_NQ; q += 256) {
        int rr = q / K3_HALO_C;
        int cc = q - rr * K3_HALO_C;
        src[q] = refl(by + rr - 1) * W_IMG + refl(bx + cc - 1);
        dst[q] = rr * K3_RSTRIDE + cc;
    }

    // Load this pixel's 72 logits into this thread's shared column + softmax
    {
        const float* lbase = g_logits + ((size_t)n * OC * H_IMG + (by + ty)) * W_IMG + bx + tx;
        float m = -1e30f;
#pragma unroll
        for (int ch = 0; ch < OC; ch++) {
            float v = lbase[(size_t)ch * (H_IMG * W_IMG)];
            lg[ch * 256 + tid] = v;
            m = fmaxf(m, v);
        }
        float s = 0.f;
#pragma unroll
        for (int ch = 0; ch < OC; ch++) {
            float e = __expf(lg[ch * 256 + tid] - m);
            lg[ch * 256 + tid] = e;
            s += e;
        }
        // fold 1/s into the stored exps so gather reads final sig directly
        float inv = 1.0f / s;
#pragma unroll
        for (int ch = 0; ch < OC; ch++)
            lg[ch * 256 + tid] *= inv;
    }
    __syncthreads();   // tables ready (lg is thread-private columns)

    // Cache this thread's table entries in registers
    const int s0 = src[tid];
    const int d0 = dst[tid];
    const bool has2 = (tid + 256) < K3_NQ;
    const int s1 = has2 ? src[tid + 256] : 0;
    const int d1 = has2 ? dst[tid + 256] : 0;

    const float* xb = x + (size_t)n * C_IN * (H_IMG * W_IMG);
    float* ob = out + (size_t)n * C_IN * (H_IMG * W_IMG)
                    + (size_t)(by + ty) * W_IMG + bx + tx;
    const int gbase = ty * K3_RSTRIDE + tx;   // gather base within channel

#pragma unroll 1
    for (int g = 0; g < 8; g++) {
        float sig[9];
#pragma unroll
        for (int k = 0; k < 9; k++) sig[k] = lg[(g * 9 + k) * 256 + tid];

#pragma unroll 1
        for (int chunk = 0; chunk < 2; chunk++) {
            const float* xcb = xb + (size_t)(g * CPG + chunk * 16) * (H_IMG * W_IMG);
            __syncthreads();   // previous xs consumed
#pragma unroll
            for (int ci = 0; ci < 16; ci++) {
                const float* c = xcb + (size_t)ci * (H_IMG * W_IMG);
                xs[ci * K3_CSTRIDE + d0] = c[s0];
                if (has2) xs[ci * K3_CSTRIDE + d1] = c[s1];
            }
            __syncthreads();

            float* op = ob + (size_t)(g * CPG + chunk * 16) * (H_IMG * W_IMG);
#pragma unroll
            for (int ci = 0; ci < 16; ci++) {
                const float* xp = xs + ci * K3_CSTRIDE + gbase;
                float acc = sig[0] * xp[0];
                acc += sig[1] * xp[1];
                acc += sig[2] * xp[2];
                acc += sig[3] * xp[K3_RSTRIDE + 0];
                acc += sig[4] * xp[K3_RSTRIDE + 1];
                acc += sig[5] * xp[K3_RSTRIDE + 2];
                acc += sig[6] * xp[2 * K3_RSTRIDE + 0];
                acc += sig[7] * xp[2 * K3_RSTRIDE + 1];
                acc += sig[8] * xp[2 * K3_RSTRIDE + 2];
                op[(size_t)ci * (H_IMG * W_IMG)] = acc;
            }
        }
    }
}

// ============================================================================
extern "C" void kernel_launch(void* const* d_in, const int* in_sizes, int n_in,
                              void* d_out, int out_size) {
    const float* x     = (const float*)d_in[0];
    const float* w     = (const float*)d_in[1];
    const float* gamma = (const float*)d_in[2];
    const float* beta  = (const float*)d_in[3];
    const float* mean  = (const float*)d_in[4];
    const float* var   = (const float*)d_in[5];
    float* out = (float*)d_out;

    cudaFuncSetAttribute(k1_conv_bn,
                         cudaFuncAttributeMaxDynamicSharedMemorySize, K1_SMEM);
    cudaFuncSetAttribute(k3_softmax_gather,
                         cudaFuncAttributeMaxDynamicSharedMemorySize, K3_SMEM);

    dim3 g1(W_IMG / K1_TW, H_IMG / K1_TH, N_BATCH * GROUPS);   // (4, 8, 128)
    k1_conv_bn<<<g1, 128, K1_SMEM>>>(x, w, gamma, beta, mean, var);

    dim3 g3(W_IMG / K3_TW, H_IMG / K3_TH, N_BATCH);            // (4, 16, 16)
    k3_softmax_gather<<<g3, 256, K3_SMEM>>>(x, out);
}

// round 4
// speedup vs baseline: 2.1203x; 1.4740x over previous
#include <cuda_runtime.h>
#include <cstdint>

// Problem constants
#define N_BATCH 16
#define C_IN    256
#define H_IMG   128
#define W_IMG   128
#define HW      (H_IMG * W_IMG)
#define GROUPS  8
#define CPG     32          // channels per group
#define KK      9           // 3x3 taps
#define OC      72          // GROUPS*KK
#define BN_EPS  1e-5f

// Logits / softmax-weights scratch: 16*72*128*128 floats = 75.5 MB
__device__ float g_logits[(size_t)N_BATCH * OC * HW];

// ---------------- f32x2 helpers (Blackwell packed fp32 FMA) ----------------
__device__ __forceinline__ void fma2(unsigned long long& d,
                                     unsigned long long a,
                                     unsigned long long b) {
    asm("fma.rn.f32x2 %0, %1, %2, %0;" : "+l"(d) : "l"(a), "l"(b));
}
__device__ __forceinline__ unsigned long long pack2(float lo, float hi) {
    unsigned long long r;
    asm("mov.b64 %0, {%1, %2};" : "=l"(r) : "f"(lo), "f"(hi));
    return r;
}
__device__ __forceinline__ void unpack2(unsigned long long v, float& lo, float& hi) {
    asm("mov.b64 {%0, %1}, %2;" : "=f"(lo), "=f"(hi) : "l"(v));
}

__device__ __forceinline__ int refl(int v) {
    return v < 0 ? -v : (v > (H_IMG - 1) ? 2 * (H_IMG - 1) - v : v);
}

// ============================================================================
// K1: grouped conv 3x3 (reflect) + BN -> logits
// Block: one (n,g), 16-row x 64-col tile, 128 threads, 8 px/thread
// (4 f32x2 pairs): each weight LDS.64 feeds 4 FMA2s. Channels staged in
// 4 chunks of 8 via a precomputed reflect-address table.
// Halo row stride padded to 68 words (mult of 4) so float4 loads are aligned.
// ============================================================================
#define K1_TW 64
#define K1_TH 16
#define K1_HALO_R 18
#define K1_HALO_C 66
#define K1_NQ (K1_HALO_R * K1_HALO_C)        // 1188
#define K1_XST 68                            // padded halo row stride (words, mult of 4)
#define K1_CHST (K1_HALO_R * K1_XST)         // 1224 words per channel
#define K1_CHUNK 8
#define K1_WS_BYTES (KK * CPG * KK * 8)                  // 20736
#define K1_XS_BYTES (K1_CHUNK * K1_CHST * 4)             // 39168
#define K1_TAB_BYTES (K1_NQ * 4)                         // 4752 each
#define K1_SMEM (K1_WS_BYTES + K1_XS_BYTES + 2 * K1_TAB_BYTES)

__global__ void __launch_bounds__(128, 3)
k1_conv_bn(const float* __restrict__ x,
           const float* __restrict__ w,
           const float* __restrict__ gamma,
           const float* __restrict__ beta,
           const float* __restrict__ mean,
           const float* __restrict__ var) {
    extern __shared__ char smem[];
    float2* ws2 = (float2*)smem;                                // [9][32][9] dup pairs
    float*  xs  = (float*)(smem + K1_WS_BYTES);                 // [8][18][68]
    int*    src = (int*)(smem + K1_WS_BYTES + K1_XS_BYTES);     // [1188]
    int*    dst = src + K1_NQ;                                  // [1188]

    const int n  = blockIdx.z >> 3;
    const int g  = blockIdx.z & 7;
    const int bx = blockIdx.x * K1_TW;
    const int by = blockIdx.y * K1_TH;
    const int tid = threadIdx.x;
    const int row = tid >> 3;            // 0..15
    const int xq  = (tid & 7) << 3;      // 0,8,...,56

    // Reflect-address tables
    for (int q = tid; q < K1_NQ; q += 128) {
        int rr = q / K1_HALO_C;
        int cc = q - rr * K1_HALO_C;
        src[q] = refl(by + rr - 1) * W_IMG + refl(bx + cc - 1);
        dst[q] = rr * K1_XST + cc;
    }

    // BN-scaled duplicated weights: ws2[o*288 + ci*9 + t]
    for (int i = tid; i < KK * CPG * KK; i += 128) {
        int o  = i / (CPG * KK);
        int oc = g * KK + o;
        float sc = gamma[oc] * rsqrtf(var[oc] + BN_EPS);
        float wv = w[(size_t)oc * (CPG * KK) + (i % (CPG * KK))] * sc;
        ws2[i] = make_float2(wv, wv);
    }

    // Accumulators (4 pairs per output channel) init with BN shift
    unsigned long long acc[9][4];
#pragma unroll
    for (int o = 0; o < 9; o++) {
        int oc = g * KK + o;
        float sc = gamma[oc] * rsqrtf(var[oc] + BN_EPS);
        float sh = beta[oc] - mean[oc] * sc;
        unsigned long long p = pack2(sh, sh);
#pragma unroll
        for (int j = 0; j < 4; j++) acc[o][j] = p;
    }

    __syncthreads();   // tables ready

    // Register-cache this thread's table entries (e=0..8 full, e=9 partial)
    int sQ[10], dQ[10];
#pragma unroll
    for (int e = 0; e < 10; e++) {
        int q = tid + e * 128;
        bool ok = (q < K1_NQ);
        sQ[e] = ok ? src[q] : 0;
        dQ[e] = ok ? dst[q] : 0;
    }
    const bool hasLast = (tid + 9 * 128) < K1_NQ;

    const float* xg = x + (size_t)(n * C_IN + g * CPG) * HW;

#pragma unroll 1
    for (int chunk = 0; chunk < 4; chunk++) {
        __syncthreads();   // previous xs consumed
        // Stage 8 channels through the reflect table
#pragma unroll 1
        for (int ci = 0; ci < K1_CHUNK; ci++) {
            const float* c = xg + (size_t)(chunk * K1_CHUNK + ci) * HW;
            float* xd = xs + ci * K1_CHST;
#pragma unroll
            for (int e = 0; e < 9; e++) xd[dQ[e]] = c[sQ[e]];
            if (hasLast) xd[dQ[9]] = c[sQ[9]];
        }
        __syncthreads();

#pragma unroll 1
        for (int ci = 0; ci < K1_CHUNK; ci++) {
            const int cig = chunk * K1_CHUNK + ci;
            const float* xrow = xs + ci * K1_CHST + row * K1_XST + xq;
            const unsigned long long* wb =
                (const unsigned long long*)(ws2) + cig * KK;

#pragma unroll
            for (int r3 = 0; r3 < 3; r3++) {
                // 10 contiguous x values for this tap row (16B-aligned base)
                float v[10];
                const float4 a0 = *(const float4*)(xrow + r3 * K1_XST);
                const float4 a1 = *(const float4*)(xrow + r3 * K1_XST + 4);
                const float2 a2 = *(const float2*)(xrow + r3 * K1_XST + 8);
                v[0]=a0.x; v[1]=a0.y; v[2]=a0.z; v[3]=a0.w;
                v[4]=a1.x; v[5]=a1.y; v[6]=a1.z; v[7]=a1.w;
                v[8]=a2.x; v[9]=a2.y;

                unsigned long long p[3][4];
#pragma unroll
                for (int c3 = 0; c3 < 3; c3++)
#pragma unroll
                    for (int j = 0; j < 4; j++)
                        p[c3][j] = pack2(v[c3 + 2 * j], v[c3 + 2 * j + 1]);

#pragma unroll
                for (int o = 0; o < 9; o++) {
                    const unsigned long long* wr = wb + o * (CPG * KK) + r3 * 3;
                    unsigned long long w0 = wr[0], w1 = wr[1], w2 = wr[2];
#pragma unroll
                    for (int j = 0; j < 4; j++) fma2(acc[o][j], p[0][j], w0);
#pragma unroll
                    for (int j = 0; j < 4; j++) fma2(acc[o][j], p[1][j], w1);
#pragma unroll
                    for (int j = 0; j < 4; j++) fma2(acc[o][j], p[2][j], w2);
                }
            }
        }
    }

    // Store logits: 2 float4 per output channel
    float* lp = g_logits + ((size_t)(n * OC + g * KK) * H_IMG + (by + row)) * W_IMG + bx + xq;
#pragma unroll
    for (int o = 0; o < 9; o++) {
        float4 r0, r1;
        unpack2(acc[o][0], r0.x, r0.y);
        unpack2(acc[o][1], r0.z, r0.w);
        unpack2(acc[o][2], r1.x, r1.y);
        unpack2(acc[o][3], r1.z, r1.w);
        *(float4*)(lp + (size_t)o * HW)     = r0;
        *(float4*)(lp + (size_t)o * HW + 4) = r1;
    }
}

// ============================================================================
// K3: softmax over 72 channels + weighted 3x3 gather (unchanged from R2-pass)
// ============================================================================
#define K3_TW 32
#define K3_TH 8
#define K3_HALO_R 10
#define K3_HALO_C 34
#define K3_NQ (K3_HALO_R * K3_HALO_C)    // 340
#define K3_CSTRIDE 352
#define K3_RSTRIDE 35

#define K3_LG_BYTES  (OC * 256 * 4)
#define K3_XS_BYTES  (16 * K3_CSTRIDE * 4)
#define K3_TAB_BYTES (K3_NQ * 4)
#define K3_SMEM (K3_LG_BYTES + K3_XS_BYTES + 2 * K3_TAB_BYTES)

__global__ void __launch_bounds__(256, 2)
k3_softmax_gather(const float* __restrict__ x, float* __restrict__ out) {
    extern __shared__ char smem[];
    float* lg  = (float*)smem;
    float* xs  = (float*)(smem + K3_LG_BYTES);
    int*   src = (int*)(smem + K3_LG_BYTES + K3_XS_BYTES);
    int*   dst = src + K3_NQ;

    const int n  = blockIdx.z;
    const int bx = blockIdx.x * K3_TW;
    const int by = blockIdx.y * K3_TH;
    const int tid = threadIdx.x;
    const int ty = tid >> 5;
    const int tx = tid & 31;

    for (int q = tid; q < K3_NQ; q += 256) {
        int rr = q / K3_HALO_C;
        int cc = q - rr * K3_HALO_C;
        src[q] = refl(by + rr - 1) * W_IMG + refl(bx + cc - 1);
        dst[q] = rr * K3_RSTRIDE + cc;
    }

    {
        const float* lbase = g_logits + ((size_t)n * OC * H_IMG + (by + ty)) * W_IMG + bx + tx;
        float m = -1e30f;
#pragma unroll
        for (int ch = 0; ch < OC; ch++) {
            float v = lbase[(size_t)ch * HW];
            lg[ch * 256 + tid] = v;
            m = fmaxf(m, v);
        }
        float s = 0.f;
#pragma unroll
        for (int ch = 0; ch < OC; ch++) {
            float e = __expf(lg[ch * 256 + tid] - m);
            lg[ch * 256 + tid] = e;
            s += e;
        }
        float inv = 1.0f / s;
#pragma unroll
        for (int ch = 0; ch < OC; ch++)
            lg[ch * 256 + tid] *= inv;
    }
    __syncthreads();

    const int s0 = src[tid];
    const int d0 = dst[tid];
    const bool has2 = (tid + 256) < K3_NQ;
    const int s1 = has2 ? src[tid + 256] : 0;
    const int d1 = has2 ? dst[tid + 256] : 0;

    const float* xb = x + (size_t)n * C_IN * HW;
    float* ob = out + (size_t)n * C_IN * HW + (size_t)(by + ty) * W_IMG + bx + tx;
    const int gbase = ty * K3_RSTRIDE + tx;

#pragma unroll 1
    for (int g = 0; g < 8; g++) {
        float sig[9];
#pragma unroll
        for (int k = 0; k < 9; k++) sig[k] = lg[(g * 9 + k) * 256 + tid];

#pragma unroll 1
        for (int chunk = 0; chunk < 2; chunk++) {
            const float* xcb = xb + (size_t)(g * CPG + chunk * 16) * HW;
            __syncthreads();
#pragma unroll
            for (int ci = 0; ci < 16; ci++) {
                const float* c = xcb + (size_t)ci * HW;
                xs[ci * K3_CSTRIDE + d0] = c[s0];
                if (has2) xs[ci * K3_CSTRIDE + d1] = c[s1];
            }
            __syncthreads();

            float* op = ob + (size_t)(g * CPG + chunk * 16) * HW;
#pragma unroll
            for (int ci = 0; ci < 16; ci++) {
                const float* xp = xs + ci * K3_CSTRIDE + gbase;
                float acc = sig[0] * xp[0];
                acc += sig[1] * xp[1];
                acc += sig[2] * xp[2];
                acc += sig[3] * xp[K3_RSTRIDE + 0];
                acc += sig[4] * xp[K3_RSTRIDE + 1];
                acc += sig[5] * xp[K3_RSTRIDE + 2];
                acc += sig[6] * xp[2 * K3_RSTRIDE + 0];
                acc += sig[7] * xp[2 * K3_RSTRIDE + 1];
                acc += sig[8] * xp[2 * K3_RSTRIDE + 2];
                op[(size_t)ci * HW] = acc;
            }
        }
    }
}

// ============================================================================
extern "C" void kernel_launch(void* const* d_in, const int* in_sizes, int n_in,
                              void* d_out, int out_size) {
    const float* x     = (const float*)d_in[0];
    const float* w     = (const float*)d_in[1];
    const float* gamma = (const float*)d_in[2];
    const float* beta  = (const float*)d_in[3];
    const float* mean  = (const float*)d_in[4];
    const float* var   = (const float*)d_in[5];
    float* out = (float*)d_out;

    cudaFuncSetAttribute(k1_conv_bn,
                         cudaFuncAttributeMaxDynamicSharedMemorySize, K1_SMEM);
    cudaFuncSetAttribute(k3_softmax_gather,
                         cudaFuncAttributeMaxDynamicSharedMemorySize, K3_SMEM);

    dim3 g1(W_IMG / K1_TW, H_IMG / K1_TH, N_BATCH * GROUPS);   // (2, 8, 128)
    k1_conv_bn<<<g1, 128, K1_SMEM>>>(x, w, gamma, beta, mean, var);

    dim3 g3(W_IMG / K3_TW, H_IMG / K3_TH, N_BATCH);            // (4, 16, 16)
    k3_softmax_gather<<<g3, 256, K3_SMEM>>>(x, out);
}

// round 5
// speedup vs baseline: 2.1244x; 1.0020x over previous
#include <cuda_runtime.h>
#include <cstdint>

// Problem constants
#define N_BATCH 16
#define C_IN    256
#define H_IMG   128
#define W_IMG   128
#define HW      (H_IMG * W_IMG)
#define GROUPS  8
#define CPG     32          // channels per group
#define KK      9           // 3x3 taps
#define OC      72          // GROUPS*KK
#define BN_EPS  1e-5f

// Logits / softmax-weights scratch: 16*72*128*128 floats = 75.5 MB
__device__ float g_logits[(size_t)N_BATCH * OC * HW];

// ---------------- f32x2 helpers (Blackwell packed fp32 FMA) ----------------
__device__ __forceinline__ void fma2(unsigned long long& d,
                                     unsigned long long a,
                                     unsigned long long b) {
    asm("fma.rn.f32x2 %0, %1, %2, %0;" : "+l"(d) : "l"(a), "l"(b));
}
__device__ __forceinline__ unsigned long long pack2(float lo, float hi) {
    unsigned long long r;
    asm("mov.b64 %0, {%1, %2};" : "=l"(r) : "f"(lo), "f"(hi));
    return r;
}
__device__ __forceinline__ void unpack2(unsigned long long v, float& lo, float& hi) {
    asm("mov.b64 {%0, %1}, %2;" : "=f"(lo), "=f"(hi) : "l"(v));
}

__device__ __forceinline__ int refl(int v) {
    return v < 0 ? -v : (v > (H_IMG - 1) ? 2 * (H_IMG - 1) - v : v);
}

// ============================================================================
// K1: grouped conv 3x3 (reflect) + BN -> logits
// Block: one (n,g), 16-row x 64-col tile, 128 threads, 8 px/thread
// (4 f32x2 pairs): each weight LDS.64 feeds 4 FMA2s. Channels staged in
// 4 chunks of 8 via a precomputed reflect-address table.
// Halo row stride padded to 68 words (mult of 4) so float4 loads are aligned.
// ============================================================================
#define K1_TW 64
#define K1_TH 16
#define K1_HALO_R 18
#define K1_HALO_C 66
#define K1_NQ (K1_HALO_R * K1_HALO_C)        // 1188
#define K1_XST 68                            // padded halo row stride (words, mult of 4)
#define K1_CHST (K1_HALO_R * K1_XST)         // 1224 words per channel
#define K1_CHUNK 8
#define K1_WS_BYTES (KK * CPG * KK * 8)                  // 20736
#define K1_XS_BYTES (K1_CHUNK * K1_CHST * 4)             // 39168
#define K1_TAB_BYTES (K1_NQ * 4)                         // 4752 each
#define K1_SMEM (K1_WS_BYTES + K1_XS_BYTES + 2 * K1_TAB_BYTES)

__global__ void __launch_bounds__(128, 3)
k1_conv_bn(const float* __restrict__ x,
           const float* __restrict__ w,
           const float* __restrict__ gamma,
           const float* __restrict__ beta,
           const float* __restrict__ mean,
           const float* __restrict__ var) {
    extern __shared__ char smem[];
    float2* ws2 = (float2*)smem;                                // [9][32][9] dup pairs
    float*  xs  = (float*)(smem + K1_WS_BYTES);                 // [8][18][68]
    int*    src = (int*)(smem + K1_WS_BYTES + K1_XS_BYTES);     // [1188]
    int*    dst = src + K1_NQ;                                  // [1188]

    const int n  = blockIdx.z >> 3;
    const int g  = blockIdx.z & 7;
    const int bx = blockIdx.x * K1_TW;
    const int by = blockIdx.y * K1_TH;
    const int tid = threadIdx.x;
    const int row = tid >> 3;            // 0..15
    const int xq  = (tid & 7) << 3;      // 0,8,...,56

    // Reflect-address tables
    for (int q = tid; q < K1_NQ; q += 128) {
        int rr = q / K1_HALO_C;
        int cc = q - rr * K1_HALO_C;
        src[q] = refl(by + rr - 1) * W_IMG + refl(bx + cc - 1);
        dst[q] = rr * K1_XST + cc;
    }

    // BN-scaled duplicated weights: ws2[o*288 + ci*9 + t]
    for (int i = tid; i < KK * CPG * KK; i += 128) {
        int o  = i / (CPG * KK);
        int oc = g * KK + o;
        float sc = gamma[oc] * rsqrtf(var[oc] + BN_EPS);
        float wv = w[(size_t)oc * (CPG * KK) + (i % (CPG * KK))] * sc;
        ws2[i] = make_float2(wv, wv);
    }

    // Accumulators (4 pairs per output channel) init with BN shift
    unsigned long long acc[9][4];
#pragma unroll
    for (int o = 0; o < 9; o++) {
        int oc = g * KK + o;
        float sc = gamma[oc] * rsqrtf(var[oc] + BN_EPS);
        float sh = beta[oc] - mean[oc] * sc;
        unsigned long long p = pack2(sh, sh);
#pragma unroll
        for (int j = 0; j < 4; j++) acc[o][j] = p;
    }

    __syncthreads();   // tables ready

    // Register-cache this thread's table entries (e=0..8 full, e=9 partial)
    int sQ[10], dQ[10];
#pragma unroll
    for (int e = 0; e < 10; e++) {
        int q = tid + e * 128;
        bool ok = (q < K1_NQ);
        sQ[e] = ok ? src[q] : 0;
        dQ[e] = ok ? dst[q] : 0;
    }
    const bool hasLast = (tid + 9 * 128) < K1_NQ;

    const float* xg = x + (size_t)(n * C_IN + g * CPG) * HW;

#pragma unroll 1
    for (int chunk = 0; chunk < 4; chunk++) {
        __syncthreads();   // previous xs consumed
        // Stage 8 channels through the reflect table
#pragma unroll 1
        for (int ci = 0; ci < K1_CHUNK; ci++) {
            const float* c = xg + (size_t)(chunk * K1_CHUNK + ci) * HW;
            float* xd = xs + ci * K1_CHST;
#pragma unroll
            for (int e = 0; e < 9; e++) xd[dQ[e]] = c[sQ[e]];
            if (hasLast) xd[dQ[9]] = c[sQ[9]];
        }
        __syncthreads();

#pragma unroll 1
        for (int ci = 0; ci < K1_CHUNK; ci++) {
            const int cig = chunk * K1_CHUNK + ci;
            const float* xrow = xs + ci * K1_CHST + row * K1_XST + xq;
            const unsigned long long* wb =
                (const unsigned long long*)(ws2) + cig * KK;

#pragma unroll
            for (int r3 = 0; r3 < 3; r3++) {
                // 10 contiguous x values for this tap row (16B-aligned base)
                float v[10];
                const float4 a0 = *(const float4*)(xrow + r3 * K1_XST);
                const float4 a1 = *(const float4*)(xrow + r3 * K1_XST + 4);
                const float2 a2 = *(const float2*)(xrow + r3 * K1_XST + 8);
                v[0]=a0.x; v[1]=a0.y; v[2]=a0.z; v[3]=a0.w;
                v[4]=a1.x; v[5]=a1.y; v[6]=a1.z; v[7]=a1.w;
                v[8]=a2.x; v[9]=a2.y;

                unsigned long long p[3][4];
#pragma unroll
                for (int c3 = 0; c3 < 3; c3++)
#pragma unroll
                    for (int j = 0; j < 4; j++)
                        p[c3][j] = pack2(v[c3 + 2 * j], v[c3 + 2 * j + 1]);

#pragma unroll
                for (int o = 0; o < 9; o++) {
                    const unsigned long long* wr = wb + o * (CPG * KK) + r3 * 3;
                    unsigned long long w0 = wr[0], w1 = wr[1], w2 = wr[2];
#pragma unroll
                    for (int j = 0; j < 4; j++) fma2(acc[o][j], p[0][j], w0);
#pragma unroll
                    for (int j = 0; j < 4; j++) fma2(acc[o][j], p[1][j], w1);
#pragma unroll
                    for (int j = 0; j < 4; j++) fma2(acc[o][j], p[2][j], w2);
                }
            }
        }
    }

    // Store logits: 2 float4 per output channel
    float* lp = g_logits + ((size_t)(n * OC + g * KK) * H_IMG + (by + row)) * W_IMG + bx + xq;
#pragma unroll
    for (int o = 0; o < 9; o++) {
        float4 r0, r1;
        unpack2(acc[o][0], r0.x, r0.y);
        unpack2(acc[o][1], r0.z, r0.w);
        unpack2(acc[o][2], r1.x, r1.y);
        unpack2(acc[o][3], r1.z, r1.w);
        *(float4*)(lp + (size_t)o * HW)     = r0;
        *(float4*)(lp + (size_t)o * HW + 4) = r1;
    }
}

// ============================================================================
// K3: softmax over 72 channels + weighted 3x3 gather (unchanged from R2-pass)
// ============================================================================
#define K3_TW 32
#define K3_TH 8
#define K3_HALO_R 10
#define K3_HALO_C 34
#define K3_NQ (K3_HALO_R * K3_HALO_C)    // 340
#define K3_CSTRIDE 352
#define K3_RSTRIDE 35

#define K3_LG_BYTES  (OC * 256 * 4)
#define K3_XS_BYTES  (16 * K3_CSTRIDE * 4)
#define K3_TAB_BYTES (K3_NQ * 4)
#define K3_SMEM (K3_LG_BYTES + K3_XS_BYTES + 2 * K3_TAB_BYTES)

__global__ void __launch_bounds__(256, 2)
k3_softmax_gather(const float* __restrict__ x, float* __restrict__ out) {
    extern __shared__ char smem[];
    float* lg  = (float*)smem;
    float* xs  = (float*)(smem + K3_LG_BYTES);
    int*   src = (int*)(smem + K3_LG_BYTES + K3_XS_BYTES);
    int*   dst = src + K3_NQ;

    const int n  = blockIdx.z;
    const int bx = blockIdx.x * K3_TW;
    const int by = blockIdx.y * K3_TH;
    const int tid = threadIdx.x;
    const int ty = tid >> 5;
    const int tx = tid & 31;

    for (int q = tid; q < K3_NQ; q += 256) {
        int rr = q / K3_HALO_C;
        int cc = q - rr * K3_HALO_C;
        src[q] = refl(by + rr - 1) * W_IMG + refl(bx + cc - 1);
        dst[q] = rr * K3_RSTRIDE + cc;
    }

    {
        const float* lbase = g_logits + ((size_t)n * OC * H_IMG + (by + ty)) * W_IMG + bx + tx;
        float m = -1e30f;
#pragma unroll
        for (int ch = 0; ch < OC; ch++) {
            float v = lbase[(size_t)ch * HW];
            lg[ch * 256 + tid] = v;
            m = fmaxf(m, v);
        }
        float s = 0.f;
#pragma unroll
        for (int ch = 0; ch < OC; ch++) {
            float e = __expf(lg[ch * 256 + tid] - m);
            lg[ch * 256 + tid] = e;
            s += e;
        }
        float inv = 1.0f / s;
#pragma unroll
        for (int ch = 0; ch < OC; ch++)
            lg[ch * 256 + tid] *= inv;
    }
    __syncthreads();

    const int s0 = src[tid];
    const int d0 = dst[tid];
    const bool has2 = (tid + 256) < K3_NQ;
    const int s1 = has2 ? src[tid + 256] : 0;
    const int d1 = has2 ? dst[tid + 256] : 0;

    const float* xb = x + (size_t)n * C_IN * HW;
    float* ob = out + (size_t)n * C_IN * HW + (size_t)(by + ty) * W_IMG + bx + tx;
    const int gbase = ty * K3_RSTRIDE + tx;

#pragma unroll 1
    for (int g = 0; g < 8; g++) {
        float sig[9];
#pragma unroll
        for (int k = 0; k < 9; k++) sig[k] = lg[(g * 9 + k) * 256 + tid];

#pragma unroll 1
        for (int chunk = 0; chunk < 2; chunk++) {
            const float* xcb = xb + (size_t)(g * CPG + chunk * 16) * HW;
            __syncthreads();
#pragma unroll
            for (int ci = 0; ci < 16; ci++) {
                const float* c = xcb + (size_t)ci * HW;
                xs[ci * K3_CSTRIDE + d0] = c[s0];
                if (has2) xs[ci * K3_CSTRIDE + d1] = c[s1];
            }
            __syncthreads();

            float* op = ob + (size_t)(g * CPG + chunk * 16) * HW;
#pragma unroll
            for (int ci = 0; ci < 16; ci++) {
                const float* xp = xs + ci * K3_CSTRIDE + gbase;
                float acc = sig[0] * xp[0];
                acc += sig[1] * xp[1];
                acc += sig[2] * xp[2];
                acc += sig[3] * xp[K3_RSTRIDE + 0];
                acc += sig[4] * xp[K3_RSTRIDE + 1];
                acc += sig[5] * xp[K3_RSTRIDE + 2];
                acc += sig[6] * xp[2 * K3_RSTRIDE + 0];
                acc += sig[7] * xp[2 * K3_RSTRIDE + 1];
                acc += sig[8] * xp[2 * K3_RSTRIDE + 2];
                op[(size_t)ci * HW] = acc;
            }
        }
    }
}

// ============================================================================
extern "C" void kernel_launch(void* const* d_in, const int* in_sizes, int n_in,
                              void* d_out, int out_size) {
    const float* x     = (const float*)d_in[0];
    const float* w     = (const float*)d_in[1];
    const float* gamma = (const float*)d_in[2];
    const float* beta  = (const float*)d_in[3];
    const float* mean  = (const float*)d_in[4];
    const float* var   = (const float*)d_in[5];
    float* out = (float*)d_out;

    cudaFuncSetAttribute(k1_conv_bn,
                         cudaFuncAttributeMaxDynamicSharedMemorySize, K1_SMEM);
    cudaFuncSetAttribute(k3_softmax_gather,
                         cudaFuncAttributeMaxDynamicSharedMemorySize, K3_SMEM);

    dim3 g1(W_IMG / K1_TW, H_IMG / K1_TH, N_BATCH * GROUPS);   // (2, 8, 128)
    k1_conv_bn<<<g1, 128, K1_SMEM>>>(x, w, gamma, beta, mean, var);

    dim3 g3(W_IMG / K3_TW, H_IMG / K3_TH, N_BATCH);            // (4, 16, 16)
    k3_softmax_gather<<<g3, 256, K3_SMEM>>>(x, out);
}